// round 8
// baseline (speedup 1.0000x reference)
#include <cuda_runtime.h>
#include <math.h>
#include <stdint.h>

#define T_TOK 8192
#define H_DIM 1024
#define F_DIM 4096
#define E_NUM 8

// ---- scratch (static device globals; no allocation at launch time) ----
__device__ int      g_count[E_NUM];
__device__ int      g_off[E_NUM];
__device__ int      g_tok[E_NUM * T_TOK];
__device__ float    g_gate[E_NUM * T_TOK];
__device__ float    g_hidden[(size_t)2 * T_TOK * F_DIM];    // fc1 out (pre-rounded)
__device__ float    g_xr[(size_t)T_TOK * H_DIM];            // rounded x
__device__ float    g_w1r[(size_t)E_NUM * H_DIM * F_DIM];   // rounded w1
__device__ float    g_w2r[(size_t)E_NUM * F_DIM * H_DIM];   // rounded w2

__device__ __forceinline__ void cp16(uint32_t dst, const float* src, uint32_t bytes) {
    asm volatile("cp.async.ca.shared.global [%0], [%1], 16, %2;"
                 :: "r"(dst), "l"(src), "r"(bytes) : "memory");
}
#define CP_COMMIT() asm volatile("cp.async.commit_group;" ::: "memory")
#define CP_WAIT(n)  asm volatile("cp.async.wait_group %0;" :: "n"(n) : "memory")

__device__ __forceinline__ void mma_tf32(float* c, const uint32_t* a, const uint32_t* b) {
    asm volatile(
        "mma.sync.aligned.m16n8k8.row.col.f32.tf32.tf32.f32 "
        "{%0,%1,%2,%3}, {%4,%5,%6,%7}, {%8,%9}, {%0,%1,%2,%3};"
        : "+f"(c[0]), "+f"(c[1]), "+f"(c[2]), "+f"(c[3])
        : "r"(a[0]), "r"(a[1]), "r"(a[2]), "r"(a[3]), "r"(b[0]), "r"(b[1]));
}

__device__ __forceinline__ float gelu_tanh(float v) {
    const float c = 0.7978845608028654f;
    float u = c * (v + 0.044715f * v * v * v);
    return 0.5f * v * (1.0f + tanhf(u));
}
// bits+0x1000 then tf32 HW truncation == cvt.rna.tf32
__device__ __forceinline__ float rna_bits(float v) {
    return __uint_as_float(__float_as_uint(v) + 0x1000u);
}

// ======================= small kernels =======================
__global__ void zero_kernel(float4* __restrict__ out4, int n4) {
    if (blockIdx.x == 0 && threadIdx.x < E_NUM) g_count[threadIdx.x] = 0;
    int stride = gridDim.x * blockDim.x;
    float4 z = make_float4(0.f, 0.f, 0.f, 0.f);
    for (int i = blockIdx.x * blockDim.x + threadIdx.x; i < n4; i += stride)
        out4[i] = z;
}

__global__ void round_kernel(const float* __restrict__ src, float* __restrict__ dst,
                             int n4) {
    int i = blockIdx.x * 256 + threadIdx.x;
    if (i < n4) {
        uint4 v = ((const uint4*)src)[i];
        v.x += 0x1000u; v.y += 0x1000u; v.z += 0x1000u; v.w += 0x1000u;
        ((uint4*)dst)[i] = v;
    }
}

// router: logits -> softmax -> top2 -> append; also emits rounded x rows.
__global__ void router_kernel(const float* __restrict__ x, const float* __restrict__ rw,
                              float* __restrict__ xr) {
    int t = blockIdx.x * 8 + threadIdx.y;
    int lane = threadIdx.x;
    float acc[E_NUM];
#pragma unroll
    for (int e = 0; e < E_NUM; e++) acc[e] = 0.0f;
    const float* xrow = x + (size_t)t * H_DIM;
    float* xrrow = xr + (size_t)t * H_DIM;
    for (int h = lane; h < H_DIM; h += 32) {
        float xv = xrow[h];
        xrrow[h] = rna_bits(xv);
        const float4* r = (const float4*)(rw + (size_t)h * E_NUM);
        float4 r0 = r[0], r1 = r[1];
        acc[0] += xv * r0.x; acc[1] += xv * r0.y;
        acc[2] += xv * r0.z; acc[3] += xv * r0.w;
        acc[4] += xv * r1.x; acc[5] += xv * r1.y;
        acc[6] += xv * r1.z; acc[7] += xv * r1.w;
    }
#pragma unroll
    for (int e = 0; e < E_NUM; e++) {
#pragma unroll
        for (int off = 16; off > 0; off >>= 1)
            acc[e] += __shfl_xor_sync(0xffffffffu, acc[e], off);
    }
    if (lane == 0) {
        float m = acc[0];
#pragma unroll
        for (int e = 1; e < E_NUM; e++) m = fmaxf(m, acc[e]);
        float p[E_NUM]; float s = 0.0f;
#pragma unroll
        for (int e = 0; e < E_NUM; e++) { p[e] = expf(acc[e] - m); s += p[e]; }
        float inv = 1.0f / s;
        int i1 = 0; float v1 = p[0];
#pragma unroll
        for (int e = 1; e < E_NUM; e++) if (p[e] > v1) { v1 = p[e]; i1 = e; }
        int i2 = -1; float v2 = -1.0f;
#pragma unroll
        for (int e = 0; e < E_NUM; e++) if (e != i1 && p[e] > v2) { v2 = p[e]; i2 = e; }
        int s1 = atomicAdd(&g_count[i1], 1);
        g_tok[i1 * T_TOK + s1]  = t;
        g_gate[i1 * T_TOK + s1] = v1 * inv;
        int s2 = atomicAdd(&g_count[i2], 1);
        g_tok[i2 * T_TOK + s2]  = t;
        g_gate[i2 * T_TOK + s2] = v2 * inv;
    }
}

__global__ void scan_kernel() {
    if (threadIdx.x == 0) {
        int s = 0;
#pragma unroll
        for (int e = 0; e < E_NUM; e++) { g_off[e] = s; s += g_count[e]; }
    }
}

// ======================= tensor-core grouped GEMM =======================
// 128x256 tile, BK=16, 256 threads (8 warps 2Mx4N), warp tile 64x64.
// 6-stage cp.async pipeline; operands pre-rounded.
// Conflict-free consumer layouts: A m-major pitch 20; B k-major pitch 264.
#define NSTAGE   6
#define A_STRIDE 10240u                          // 128*20*4
#define B_OFF    (NSTAGE * A_STRIDE)             // 61440
#define B_STRIDE 16896u                          // 16*264*4
#define SMEM_BYTES (B_OFF + NSTAGE * B_STRIDE)   // 162816

template<int KTOT, int LDB, bool FC1>
__global__ void __launch_bounds__(256, 1)
moe_gemm(const float* __restrict__ Asrc, const float* __restrict__ W,
         float* __restrict__ Out)
{
    extern __shared__ char sm[];
    const int e = blockIdx.z;
    const int n = g_count[e];
    const int row0 = blockIdx.y * 128;
    if (row0 >= n) return;
    const int col0 = blockIdx.x * 256;

    const uint32_t sbase = (uint32_t)__cvta_generic_to_shared(sm);
    const int tid = threadIdx.x;
    const int lane = tid & 31;
    const int w = tid >> 5;
    const int wm = w & 1;        // 0..1 (64 rows)
    const int wn = w >> 1;       // 0..3 (64 cols)

    // ---- producer mapping (coalesced) ----
    const int am = tid >> 1;
    const int ak = (tid & 1) * 8;
    const float* aptr = Asrc;
    uint32_t abytes = 0;
    if (row0 + am < n) {
        abytes = 16;
        if (FC1) aptr = Asrc + (size_t)g_tok[e * T_TOK + row0 + am] * H_DIM + ak;
        else     aptr = g_hidden + (size_t)(g_off[e] + row0 + am) * F_DIM + ak;
    }
    const int bk = tid >> 4;
    const int bn0 = (tid & 15) * 4;
    const float* bptr = W + (size_t)e * KTOT * LDB + (size_t)bk * LDB + col0 + bn0;

    const uint32_t dA = sbase + (uint32_t)(am * 20 + ak) * 4u;
    const uint32_t dB = sbase + B_OFF + (uint32_t)(bk * 264 + bn0) * 4u;

    auto issue = [&](int s) {
        int st = s % NSTAGE;
        int k0 = s * 16;
        uint32_t da = dA + (uint32_t)st * A_STRIDE;
        cp16(da,      aptr + k0,     abytes);
        cp16(da + 16, aptr + k0 + 4, abytes);
        uint32_t db = dB + (uint32_t)st * B_STRIDE;
        const float* bp = bptr + (size_t)k0 * LDB;
#pragma unroll
        for (int c = 0; c < 4; c++)
            cp16(db + (uint32_t)c * 256u, bp + c * 64, 16);
    };

    float acc[4][8][4];
#pragma unroll
    for (int i = 0; i < 4; i++)
#pragma unroll
        for (int j = 0; j < 8; j++)
#pragma unroll
            for (int q = 0; q < 4; q++) acc[i][j][q] = 0.0f;

    const int gq = lane >> 2;
    const int kq4 = lane & 3;

    auto compute = [&](int st) {
        const uint32_t* Asm = (const uint32_t*)(sm + st * A_STRIDE);
        const uint32_t* Bsm = (const uint32_t*)(sm + B_OFF + st * B_STRIDE);
#pragma unroll
        for (int kq = 0; kq < 16; kq += 8) {
            const int kr = kq + kq4;
            uint32_t af[4][4], bf[8][2];
#pragma unroll
            for (int mf = 0; mf < 4; mf++) {
                int m = wm * 64 + mf * 16 + gq;
                af[mf][0] = Asm[m * 20 + kr];
                af[mf][1] = Asm[(m + 8) * 20 + kr];
                af[mf][2] = Asm[m * 20 + kr + 4];
                af[mf][3] = Asm[(m + 8) * 20 + kr + 4];
            }
#pragma unroll
            for (int nf = 0; nf < 8; nf++) {
                int nn = wn * 64 + nf * 8 + gq;
                bf[nf][0] = Bsm[kr * 264 + nn];
                bf[nf][1] = Bsm[(kr + 4) * 264 + nn];
            }
#pragma unroll
            for (int mf = 0; mf < 4; mf++)
#pragma unroll
                for (int nf = 0; nf < 8; nf++)
                    mma_tf32(acc[mf][nf], af[mf], bf[nf]);
        }
    };

    constexpr int S = KTOT / 16;
    issue(0); CP_COMMIT();
    issue(1); CP_COMMIT();
    issue(2); CP_COMMIT();
    issue(3); CP_COMMIT();
    issue(4); CP_COMMIT();
#pragma unroll 1
    for (int s = 0; s < S; s++) {
        CP_WAIT(4);
        __syncthreads();
        if (s + 5 < S) issue(s + 5);
        CP_COMMIT();
        compute(s % NSTAGE);
    }

    // ---- epilogue ----
    if (FC1) {
        const int hrow0 = g_off[e];
#pragma unroll
        for (int mf = 0; mf < 4; mf++) {
            int rlo = row0 + wm * 64 + mf * 16 + gq;
            int rhi = rlo + 8;
            float* dlo = g_hidden + (size_t)(hrow0 + rlo) * F_DIM;
            float* dhi = g_hidden + (size_t)(hrow0 + rhi) * F_DIM;
#pragma unroll
            for (int nf = 0; nf < 8; nf++) {
                int c = col0 + wn * 64 + nf * 8 + 2 * kq4;
                if (rlo < n) {
                    float2 v = make_float2(rna_bits(gelu_tanh(acc[mf][nf][0])),
                                           rna_bits(gelu_tanh(acc[mf][nf][1])));
                    *(float2*)(dlo + c) = v;
                }
                if (rhi < n) {
                    float2 v = make_float2(rna_bits(gelu_tanh(acc[mf][nf][2])),
                                           rna_bits(gelu_tanh(acc[mf][nf][3])));
                    *(float2*)(dhi + c) = v;
                }
            }
        }
    } else {
        // direct gate-weighted combine via RED (no g_y round-trip)
#pragma unroll
        for (int mf = 0; mf < 4; mf++) {
            int rlo = row0 + wm * 64 + mf * 16 + gq;
            int rhi = rlo + 8;
            int tok_lo = 0, tok_hi = 0; float gl = 0.f, gh = 0.f;
            if (rlo < n) { tok_lo = g_tok[e * T_TOK + rlo]; gl = g_gate[e * T_TOK + rlo]; }
            if (rhi < n) { tok_hi = g_tok[e * T_TOK + rhi]; gh = g_gate[e * T_TOK + rhi]; }
            float* olo = Out + (size_t)tok_lo * H_DIM;
            float* ohi = Out + (size_t)tok_hi * H_DIM;
#pragma unroll
            for (int nf = 0; nf < 8; nf++) {
                int c = col0 + wn * 64 + nf * 8 + 2 * kq4;
                if (rlo < n) {
                    atomicAdd(olo + c,     gl * acc[mf][nf][0]);
                    atomicAdd(olo + c + 1, gl * acc[mf][nf][1]);
                }
                if (rhi < n) {
                    atomicAdd(ohi + c,     gh * acc[mf][nf][2]);
                    atomicAdd(ohi + c + 1, gh * acc[mf][nf][3]);
                }
            }
        }
    }
}

// ======================= launch =======================
extern "C" void kernel_launch(void* const* d_in, const int* in_sizes, int n_in,
                              void* d_out, int out_size) {
    const float* x  = (const float*)d_in[0];
    const float* rw = (const float*)d_in[1];
    const float* w1 = (const float*)d_in[2];
    const float* w2 = (const float*)d_in[3];
    float* out = (float*)d_out;

    cudaFuncSetAttribute(moe_gemm<H_DIM, F_DIM, true>,
                         cudaFuncAttributeMaxDynamicSharedMemorySize, SMEM_BYTES);
    cudaFuncSetAttribute(moe_gemm<F_DIM, H_DIM, false>,
                         cudaFuncAttributeMaxDynamicSharedMemorySize, SMEM_BYTES);

    float* xr  = nullptr; cudaGetSymbolAddress((void**)&xr,  g_xr);
    float* w1r = nullptr; cudaGetSymbolAddress((void**)&w1r, g_w1r);
    float* w2r = nullptr; cudaGetSymbolAddress((void**)&w2r, g_w2r);

    zero_kernel<<<4096, 256>>>((float4*)out, out_size / 4);
    router_kernel<<<T_TOK / 8, dim3(32, 8)>>>(x, rw, xr);
    round_kernel<<<(E_NUM * H_DIM * F_DIM / 4 + 255) / 256, 256>>>(w1, w1r, E_NUM * H_DIM * F_DIM / 4);
    round_kernel<<<(E_NUM * F_DIM * H_DIM / 4 + 255) / 256, 256>>>(w2, w2r, E_NUM * F_DIM * H_DIM / 4);
    scan_kernel<<<1, 32>>>();
    moe_gemm<H_DIM, F_DIM, true ><<<dim3(F_DIM / 256, T_TOK / 128, E_NUM), 256, SMEM_BYTES>>>(xr, w1r, nullptr);
    moe_gemm<F_DIM, H_DIM, false><<<dim3(H_DIM / 256, T_TOK / 128, E_NUM), 256, SMEM_BYTES>>>(nullptr, w2r, out);
}

// round 9
// speedup vs baseline: 2.0855x; 2.0855x over previous
#include <cuda_runtime.h>
#include <cuda_fp16.h>
#include <math.h>
#include <stdint.h>

#define T_TOK 8192
#define H_DIM 1024
#define F_DIM 4096
#define E_NUM 8

// ---- scratch (static device globals; no allocation at launch time) ----
__device__ int      g_count[E_NUM];
__device__ int      g_off[E_NUM];
__device__ int      g_tok[E_NUM * T_TOK];
__device__ float    g_gate[E_NUM * T_TOK];
__device__ uint32_t g_sel[2 * T_TOK];                       // (expert<<16)|slot
__device__ __half   g_xh[(size_t)T_TOK * H_DIM];            // fp16 x
__device__ __half   g_w1h[(size_t)E_NUM * H_DIM * F_DIM];   // fp16 w1
__device__ __half   g_w2h[(size_t)E_NUM * F_DIM * H_DIM];   // fp16 w2
__device__ __half   g_hidden[(size_t)2 * T_TOK * F_DIM];    // fc1 out fp16
__device__ float    g_y[(size_t)2 * T_TOK * H_DIM];         // fc2 per-slot out

__device__ __forceinline__ void cp16(uint32_t dst, const void* src, uint32_t bytes) {
    asm volatile("cp.async.ca.shared.global [%0], [%1], 16, %2;"
                 :: "r"(dst), "l"(src), "r"(bytes) : "memory");
}
#define CP_COMMIT() asm volatile("cp.async.commit_group;" ::: "memory")
#define CP_WAIT(n)  asm volatile("cp.async.wait_group %0;" :: "n"(n) : "memory")

__device__ __forceinline__ void ldsm_x4(uint32_t* r, uint32_t addr) {
    asm volatile("ldmatrix.sync.aligned.m8n8.x4.shared.b16 {%0,%1,%2,%3}, [%4];"
                 : "=r"(r[0]), "=r"(r[1]), "=r"(r[2]), "=r"(r[3]) : "r"(addr));
}
__device__ __forceinline__ void ldsm_x4_t(uint32_t* r, uint32_t addr) {
    asm volatile("ldmatrix.sync.aligned.m8n8.x4.trans.shared.b16 {%0,%1,%2,%3}, [%4];"
                 : "=r"(r[0]), "=r"(r[1]), "=r"(r[2]), "=r"(r[3]) : "r"(addr));
}
__device__ __forceinline__ void mma_f16(float* c, const uint32_t* a, const uint32_t* b) {
    asm volatile(
        "mma.sync.aligned.m16n8k16.row.col.f32.f16.f16.f32 "
        "{%0,%1,%2,%3}, {%4,%5,%6,%7}, {%8,%9}, {%0,%1,%2,%3};"
        : "+f"(c[0]), "+f"(c[1]), "+f"(c[2]), "+f"(c[3])
        : "r"(a[0]), "r"(a[1]), "r"(a[2]), "r"(a[3]), "r"(b[0]), "r"(b[1]));
}

__device__ __forceinline__ float gelu_tanh(float v) {
    const float c = 0.7978845608028654f;
    float u = c * (v + 0.044715f * v * v * v);
    return 0.5f * v * (1.0f + tanhf(u));
}

// ======================= small kernels =======================
__global__ void zero_kernel() {
    if (threadIdx.x < E_NUM) g_count[threadIdx.x] = 0;
}

// fp32 -> fp16 convert, 8 elems/thread (16B stores)
__global__ void cvt_kernel(const float* __restrict__ src, __half* __restrict__ dst,
                           int n8) {
    int i = blockIdx.x * 256 + threadIdx.x;
    if (i < n8) {
        float4 a = ((const float4*)src)[2 * i];
        float4 b = ((const float4*)src)[2 * i + 1];
        __half2 h[4];
        h[0] = __floats2half2_rn(a.x, a.y);
        h[1] = __floats2half2_rn(a.z, a.w);
        h[2] = __floats2half2_rn(b.x, b.y);
        h[3] = __floats2half2_rn(b.z, b.w);
        ((uint4*)dst)[i] = *(uint4*)h;
    }
}

// router: logits -> softmax -> top2 -> append; also emits fp16 x rows.
__global__ void router_kernel(const float* __restrict__ x, const float* __restrict__ rw,
                              __half* __restrict__ xh) {
    int t = blockIdx.x * 8 + threadIdx.y;
    int lane = threadIdx.x;
    float acc[E_NUM];
#pragma unroll
    for (int e = 0; e < E_NUM; e++) acc[e] = 0.0f;
    const float* xrow = x + (size_t)t * H_DIM;
    __half* xhrow = xh + (size_t)t * H_DIM;
    for (int h = lane; h < H_DIM; h += 32) {
        float xv = xrow[h];
        xhrow[h] = __float2half_rn(xv);
        const float4* r = (const float4*)(rw + (size_t)h * E_NUM);
        float4 r0 = r[0], r1 = r[1];
        acc[0] += xv * r0.x; acc[1] += xv * r0.y;
        acc[2] += xv * r0.z; acc[3] += xv * r0.w;
        acc[4] += xv * r1.x; acc[5] += xv * r1.y;
        acc[6] += xv * r1.z; acc[7] += xv * r1.w;
    }
#pragma unroll
    for (int e = 0; e < E_NUM; e++) {
#pragma unroll
        for (int off = 16; off > 0; off >>= 1)
            acc[e] += __shfl_xor_sync(0xffffffffu, acc[e], off);
    }
    if (lane == 0) {
        float m = acc[0];
#pragma unroll
        for (int e = 1; e < E_NUM; e++) m = fmaxf(m, acc[e]);
        float p[E_NUM]; float s = 0.0f;
#pragma unroll
        for (int e = 0; e < E_NUM; e++) { p[e] = expf(acc[e] - m); s += p[e]; }
        float inv = 1.0f / s;
        int i1 = 0; float v1 = p[0];
#pragma unroll
        for (int e = 1; e < E_NUM; e++) if (p[e] > v1) { v1 = p[e]; i1 = e; }
        int i2 = -1; float v2 = -1.0f;
#pragma unroll
        for (int e = 0; e < E_NUM; e++) if (e != i1 && p[e] > v2) { v2 = p[e]; i2 = e; }
        int s1 = atomicAdd(&g_count[i1], 1);
        g_tok[i1 * T_TOK + s1]  = t;
        g_gate[i1 * T_TOK + s1] = v1 * inv;
        g_sel[2 * t]            = ((uint32_t)i1 << 16) | (uint32_t)s1;
        int s2 = atomicAdd(&g_count[i2], 1);
        g_tok[i2 * T_TOK + s2]  = t;
        g_gate[i2 * T_TOK + s2] = v2 * inv;
        g_sel[2 * t + 1]        = ((uint32_t)i2 << 16) | (uint32_t)s2;
    }
}

__global__ void scan_kernel() {
    if (threadIdx.x == 0) {
        int s = 0;
#pragma unroll
        for (int e = 0; e < E_NUM; e++) { g_off[e] = s; s += g_count[e]; }
    }
}

__global__ void combine_kernel(float* __restrict__ out) {
    int idx = blockIdx.x * 256 + threadIdx.x;
    int t  = idx >> 8;
    int h4 = idx & 255;
    uint32_t va = g_sel[2 * t], vb = g_sel[2 * t + 1];
    int ea = va >> 16, sa = va & 0xFFFF;
    int eb = vb >> 16, sb = vb & 0xFFFF;
    float ga = g_gate[ea * T_TOK + sa];
    float gb = g_gate[eb * T_TOK + sb];
    size_t ra = (size_t)(g_off[ea] + sa) * H_DIM + h4 * 4;
    size_t rb = (size_t)(g_off[eb] + sb) * H_DIM + h4 * 4;
    float4 ya = *(const float4*)(g_y + ra);
    float4 yb = *(const float4*)(g_y + rb);
    float4 o;
    o.x = ga * ya.x + gb * yb.x;
    o.y = ga * ya.y + gb * yb.y;
    o.z = ga * ya.z + gb * yb.z;
    o.w = ga * ya.w + gb * yb.w;
    *(float4*)(out + (size_t)t * H_DIM + h4 * 4) = o;
}

// ======================= fp16 tensor-core grouped GEMM =======================
// 128x256 tile, BK=16, 256 threads (8 warps 2Mx4N), warp tile 64x64.
// mma m16n8k16 f16->f32, ldmatrix fragment loads, 4-stage cp.async.
// A smem: [128 rows][48B]  (16 halves + 8 pad; 48/16=3 odd -> ldsm conflict-free)
// B smem: [16 k-rows][528B] (256 halves + 8 pad; 528/16=33 odd)
#define NSTAGE   4
#define A_PITCH  48u
#define A_STRIDE 6144u                           // 128*48
#define B_PITCH  528u
#define B_STRIDE 8448u                           // 16*528
#define B_OFF    (NSTAGE * A_STRIDE)             // 24576
#define SMEM_BYTES (B_OFF + NSTAGE * B_STRIDE)   // 58368

template<int KTOT, int LDA, int LDB, bool FC1>
__global__ void __launch_bounds__(256, 1)
moe_gemm(const __half* __restrict__ Asrc, const __half* __restrict__ W)
{
    extern __shared__ char sm[];
    const int e = blockIdx.z;
    const int n = g_count[e];
    const int row0 = blockIdx.y * 128;
    if (row0 >= n) return;
    const int col0 = blockIdx.x * 256;

    const uint32_t sbase = (uint32_t)__cvta_generic_to_shared(sm);
    const int tid = threadIdx.x;
    const int lane = tid & 31;
    const int w = tid >> 5;
    const int wm = w & 1;        // 0..1 (64 rows)
    const int wn = w >> 1;       // 0..3 (64 cols)

    // ---- producer mapping (coalesced) ----
    const int am = tid >> 1;                  // A row, 2 thr/row (16B each)
    const int ah = (tid & 1) * 8;             // half offset
    const __half* aptr = Asrc;
    uint32_t abytes = 0;
    if (row0 + am < n) {
        abytes = 16;
        if (FC1) aptr = Asrc + (size_t)g_tok[e * T_TOK + row0 + am] * LDA + ah;
        else     aptr = Asrc + (size_t)(g_off[e] + row0 + am) * LDA + ah;
    }
    const int bk = tid >> 4;                  // k-row 0..15
    const int bh = (tid & 15) * 16;           // half col base (32B per thread)
    const __half* bptr = W + (size_t)e * KTOT * LDB + (size_t)bk * LDB + col0 + bh;

    const uint32_t dA = sbase + (uint32_t)am * A_PITCH + (uint32_t)(tid & 1) * 16u;
    const uint32_t dB = sbase + B_OFF + (uint32_t)bk * B_PITCH + (uint32_t)(tid & 15) * 32u;

    auto issue = [&](int s) {
        int st = s & (NSTAGE - 1);
        uint32_t da = dA + (uint32_t)st * A_STRIDE;
        cp16(da, aptr + (size_t)s * 16, abytes);
        uint32_t db = dB + (uint32_t)st * B_STRIDE;
        const __half* bp = bptr + (size_t)s * 16 * LDB;
        cp16(db,      bp,     16);
        cp16(db + 16, bp + 8, 16);
    };

    float acc[4][8][4];
#pragma unroll
    for (int i = 0; i < 4; i++)
#pragma unroll
        for (int j = 0; j < 8; j++)
#pragma unroll
            for (int q = 0; q < 4; q++) acc[i][j][q] = 0.0f;

    // ldmatrix per-lane offsets
    // A x4: lanes 0-7 rows m+0..7 k0 | 8-15 rows m+8..15 k0 | 16-23 rows m+0..7 k8 | 24-31 rows m+8..15 k8
    const uint32_t aoff = (uint32_t)(((lane & 7) + ((lane >> 3) & 1) * 8) * A_PITCH
                                     + (lane >> 4) * 16);
    // B x4 trans: lanes 0-15 k-rows 0..15 at n0 | lanes 16-31 k-rows 0..15 at n0+8
    const uint32_t boff = (uint32_t)((lane & 15) * B_PITCH + (lane >> 4) * 16);

    auto compute = [&](int st) {
        const uint32_t sA = sbase + (uint32_t)st * A_STRIDE + aoff;
        const uint32_t sB = sbase + B_OFF + (uint32_t)st * B_STRIDE + boff;
        uint32_t af[4][4], bf[4][4];
#pragma unroll
        for (int mf = 0; mf < 4; mf++)
            ldsm_x4(af[mf], sA + (uint32_t)(wm * 64 + mf * 16) * A_PITCH);
#pragma unroll
        for (int p = 0; p < 4; p++)
            ldsm_x4_t(bf[p], sB + (uint32_t)(wn * 128 + p * 32));
#pragma unroll
        for (int mf = 0; mf < 4; mf++)
#pragma unroll
            for (int p = 0; p < 4; p++) {
                mma_f16(acc[mf][2 * p],     af[mf], bf[p]);
                mma_f16(acc[mf][2 * p + 1], af[mf], bf[p] + 2);
            }
    };

    constexpr int S = KTOT / 16;
    issue(0); CP_COMMIT();
    issue(1); CP_COMMIT();
    issue(2); CP_COMMIT();
#pragma unroll 1
    for (int s = 0; s < S; s++) {
        CP_WAIT(2);
        __syncthreads();
        if (s + 3 < S) issue(s + 3);
        CP_COMMIT();
        compute(s & (NSTAGE - 1));
    }

    // ---- epilogue ----
    const int gq = lane >> 2;
    const int kq4 = lane & 3;
    if (FC1) {
        const int hrow0 = g_off[e];
#pragma unroll
        for (int mf = 0; mf < 4; mf++) {
            int rlo = row0 + wm * 64 + mf * 16 + gq;
            int rhi = rlo + 8;
            __half* dlo = g_hidden + (size_t)(hrow0 + rlo) * F_DIM;
            __half* dhi = g_hidden + (size_t)(hrow0 + rhi) * F_DIM;
#pragma unroll
            for (int nf = 0; nf < 8; nf++) {
                int c = col0 + wn * 64 + nf * 8 + 2 * kq4;
                if (rlo < n) {
                    __half2 v = __floats2half2_rn(gelu_tanh(acc[mf][nf][0]),
                                                  gelu_tanh(acc[mf][nf][1]));
                    *(__half2*)(dlo + c) = v;
                }
                if (rhi < n) {
                    __half2 v = __floats2half2_rn(gelu_tanh(acc[mf][nf][2]),
                                                  gelu_tanh(acc[mf][nf][3]));
                    *(__half2*)(dhi + c) = v;
                }
            }
        }
    } else {
        const int yrow0 = g_off[e];
#pragma unroll
        for (int mf = 0; mf < 4; mf++) {
            int rlo = row0 + wm * 64 + mf * 16 + gq;
            int rhi = rlo + 8;
            float* dlo = g_y + (size_t)(yrow0 + rlo) * H_DIM;
            float* dhi = g_y + (size_t)(yrow0 + rhi) * H_DIM;
#pragma unroll
            for (int nf = 0; nf < 8; nf++) {
                int c = col0 + wn * 64 + nf * 8 + 2 * kq4;
                if (rlo < n)
                    *(float2*)(dlo + c) = make_float2(acc[mf][nf][0], acc[mf][nf][1]);
                if (rhi < n)
                    *(float2*)(dhi + c) = make_float2(acc[mf][nf][2], acc[mf][nf][3]);
            }
        }
    }
}

// ======================= launch =======================
extern "C" void kernel_launch(void* const* d_in, const int* in_sizes, int n_in,
                              void* d_out, int out_size) {
    const float* x  = (const float*)d_in[0];
    const float* rw = (const float*)d_in[1];
    const float* w1 = (const float*)d_in[2];
    const float* w2 = (const float*)d_in[3];
    float* out = (float*)d_out;

    cudaFuncSetAttribute(moe_gemm<H_DIM, H_DIM, F_DIM, true>,
                         cudaFuncAttributeMaxDynamicSharedMemorySize, SMEM_BYTES);
    cudaFuncSetAttribute(moe_gemm<F_DIM, F_DIM, H_DIM, false>,
                         cudaFuncAttributeMaxDynamicSharedMemorySize, SMEM_BYTES);

    __half* xh  = nullptr; cudaGetSymbolAddress((void**)&xh,  g_xh);
    __half* w1h = nullptr; cudaGetSymbolAddress((void**)&w1h, g_w1h);
    __half* w2h = nullptr; cudaGetSymbolAddress((void**)&w2h, g_w2h);
    __half* hid = nullptr; cudaGetSymbolAddress((void**)&hid, g_hidden);

    const int wcount8 = E_NUM * H_DIM * F_DIM / 8;
    zero_kernel<<<1, 32>>>();
    router_kernel<<<T_TOK / 8, dim3(32, 8)>>>(x, rw, xh);
    cvt_kernel<<<(wcount8 + 255) / 256, 256>>>(w1, w1h, wcount8);
    cvt_kernel<<<(wcount8 + 255) / 256, 256>>>(w2, w2h, wcount8);
    scan_kernel<<<1, 32>>>();
    moe_gemm<H_DIM, H_DIM, F_DIM, true ><<<dim3(F_DIM / 256, T_TOK / 128, E_NUM), 256, SMEM_BYTES>>>(xh, w1h);
    moe_gemm<F_DIM, F_DIM, H_DIM, false><<<dim3(H_DIM / 256, T_TOK / 128, E_NUM), 256, SMEM_BYTES>>>(hid, w2h);
    combine_kernel<<<(T_TOK * H_DIM / 4) / 256, 256>>>(out);
}